// round 9
// baseline (speedup 1.0000x reference)
#include <cuda_runtime.h>
#include <cuda_fp16.h>
#include <cstdint>

// Shapes (fixed)
#define NB 4
#define NN 512
#define ND 2
#define NH 64
#define NO 2

// ---------------------------------------------------------------------------
__device__ __forceinline__ uint32_t smem_u32(const void* p) {
    uint32_t a;
    asm("{ .reg .u64 t; cvta.to.shared.u64 t, %1; cvt.u32.u64 %0, t; }" : "=r"(a) : "l"(p));
    return a;
}
__device__ __forceinline__ uint32_t pack_f16x2(float a, float b) {
    uint32_t r;
    asm("cvt.rn.f16x2.f32 %0, %2, %1;" : "=r"(r) : "f"(a), "f"(b));
    return r;
}
__device__ __forceinline__ void ldsm_x4(uint32_t& a0, uint32_t& a1, uint32_t& a2,
                                        uint32_t& a3, uint32_t addr) {
    asm volatile("ldmatrix.sync.aligned.m8n8.x4.shared.b16 {%0,%1,%2,%3}, [%4];"
                 : "=r"(a0), "=r"(a1), "=r"(a2), "=r"(a3) : "r"(addr));
}
__device__ __forceinline__ void ldsm_x2(uint32_t& b0, uint32_t& b1, uint32_t addr) {
    asm volatile("ldmatrix.sync.aligned.m8n8.x2.shared.b16 {%0,%1}, [%2];"
                 : "=r"(b0), "=r"(b1) : "r"(addr));
}
__device__ __forceinline__ void mma16816(float& c0, float& c1, float& c2, float& c3,
                                         uint32_t a0, uint32_t a1, uint32_t a2, uint32_t a3,
                                         uint32_t b0, uint32_t b1) {
    asm volatile("mma.sync.aligned.m16n8k16.row.col.f32.f16.f16.f32 "
                 "{%0,%1,%2,%3}, {%4,%5,%6,%7}, {%8,%9}, {%0,%1,%2,%3};"
                 : "+f"(c0), "+f"(c1), "+f"(c2), "+f"(c3)
                 : "r"(a0), "r"(a1), "r"(a2), "r"(a3), "r"(b0), "r"(b1));
}

#define TSTR 72
#define WSTR 72

// ---------------------------------------------------------------------------
// Fully fused kernel: one CTA per (b,i), 256 thr.
// Edge phase: T built from x in registers (no LDG in mainloop), HMMA GEMM,
// fused relu(+b2)*adj epilogue -> s[64] in SMEM.
// Node phase (fused tail): 3 GEMV layers + output, 4 partial-k threads per h.
// ---------------------------------------------------------------------------
__global__ void __launch_bounds__(256, 2) k_fused(const float* __restrict__ x,
                                                  const float* __restrict__ adj,
                                                  const float* __restrict__ Wn2e,
                                                  const float* __restrict__ bn2e,
                                                  const float* __restrict__ We2e,
                                                  const float* __restrict__ be2e,
                                                  const float* __restrict__ We2n,
                                                  const float* __restrict__ be2n,
                                                  const float* __restrict__ Wn2n,
                                                  const float* __restrict__ bn2n,
                                                  const float* __restrict__ Wo1,
                                                  const float* __restrict__ bo1,
                                                  const float* __restrict__ Wo2,
                                                  const float* __restrict__ bo2,
                                                  float* __restrict__ out) {
    __shared__ __align__(16) __half Tsh[2][128 * TSTR];
    __shared__ __align__(16) char wpool[64 * WSTR * 2];   // Wsh then sx
    __shared__ float su[64];
    __shared__ float sb2[64];
    __shared__ float red[8][32];

    __half* Wsh = (__half*)wpool;
    float* sx = (float*)wpool;      // [512][2] after B-fragment hoist

    // tail buffers alias Tsh (dead after mainloop)
    float* sfin = (float*)Tsh;           // [64]
    float* part = sfin + 64;             // [4*64]
    float* hA   = part + 256;            // [64]
    float* hB   = hA + 64;               // [64]

    int t = threadIdx.x;
    int w = t >> 5;
    int lane = t & 31;
    int bi = blockIdx.x;
    int b = bi >> 9;
    int i = bi & 511;
    int mq = w & 3;
    int nq = w >> 2;

    uint32_t Tb0 = smem_u32(Tsh[0]);
    uint32_t Tb1 = smem_u32(Tsh[1]);
    uint32_t Wb = smem_u32(wpool);

    // ---- stage W_e2e [64h][64k] as fp16 ----
    {
        int h = t >> 2;
        int kb = (t & 3) * 16;
        const float* wrow = We2e + h * 64 + kb;
        #pragma unroll
        for (int c = 0; c < 2; ++c) {
            float4 f0 = *(const float4*)(wrow + c * 8);
            float4 f1 = *(const float4*)(wrow + c * 8 + 4);
            uint4 pk;
            pk.x = pack_f16x2(f0.x, f0.y);
            pk.y = pack_f16x2(f0.z, f0.w);
            pk.z = pack_f16x2(f1.x, f1.y);
            pk.w = pack_f16x2(f1.z, f1.w);
            *(uint4*)(Wsh + h * WSTR + kb + c * 8) = pk;
        }
    }
    if (t < 64) {
        float4 wr = *(const float4*)(Wn2e + t * 4);
        float xi0 = x[(b * NN + i) * 2 + 0];
        float xi1 = x[(b * NN + i) * 2 + 1];
        su[t]  = bn2e[t] + wr.x * xi0 + wr.y * xi1;
        sb2[t] = be2e[t];
    }
    __syncthreads();

    // ---- hoist B fragments ----
    uint32_t Bfr[4][4][2];
    #pragma unroll
    for (int k = 0; k < 4; ++k) {
        #pragma unroll
        for (int nt = 0; nt < 4; ++nt) {
            uint32_t addr = Wb + (uint32_t)(((nq * 32 + nt * 8 + (lane & 7)) * WSTR
                                             + k * 16 + ((lane >> 3) & 1) * 8) * 2);
            ldsm_x2(Bfr[k][nt][0], Bfr[k][nt][1], addr);
        }
    }
    __syncthreads();   // Wsh dead

    // ---- stage x (batch b, 512 nodes x 2) ----
    {
        const float* xb = x + b * NN * 2;
        for (int idx = t; idx < NN * 2 / 4; idx += 256)
            ((float4*)sx)[idx] = ((const float4*)xb)[idx];
    }

    int ko = (t & 7) * 8;
    int jrow4 = (t >> 3) * 4;
    float w2r[8], w3r[8], ur[8];
    #pragma unroll
    for (int kk = 0; kk < 8; ++kk) {
        float4 wr = *(const float4*)(Wn2e + (ko + kk) * 4);
        w2r[kk] = wr.z;
        w3r[kk] = wr.w;
    }
    __syncthreads();
    #pragma unroll
    for (int kk = 0; kk < 8; ++kk) ur[kk] = su[ko + kk];

    const float* adjrow = adj + i * NN;

    float sacc[8];
    #pragma unroll
    for (int q = 0; q < 8; ++q) sacc[q] = 0.f;

    int a_row = lane & 15;
    int a_kh = lane >> 4;

    // ---- build tile 0 ----
    {
        __half* tb = Tsh[0];
        #pragma unroll
        for (int jj = 0; jj < 4; ++jj) {
            int j = jrow4 + jj;
            float x0 = sx[j * 2 + 0];
            float x1 = sx[j * 2 + 1];
            uint4 pk;
            float r0 = fmaxf(fmaf(w3r[0], x1, fmaf(w2r[0], x0, ur[0])), 0.f);
            float r1 = fmaxf(fmaf(w3r[1], x1, fmaf(w2r[1], x0, ur[1])), 0.f);
            float r2 = fmaxf(fmaf(w3r[2], x1, fmaf(w2r[2], x0, ur[2])), 0.f);
            float r3 = fmaxf(fmaf(w3r[3], x1, fmaf(w2r[3], x0, ur[3])), 0.f);
            float r4 = fmaxf(fmaf(w3r[4], x1, fmaf(w2r[4], x0, ur[4])), 0.f);
            float r5 = fmaxf(fmaf(w3r[5], x1, fmaf(w2r[5], x0, ur[5])), 0.f);
            float r6 = fmaxf(fmaf(w3r[6], x1, fmaf(w2r[6], x0, ur[6])), 0.f);
            float r7 = fmaxf(fmaf(w3r[7], x1, fmaf(w2r[7], x0, ur[7])), 0.f);
            pk.x = pack_f16x2(r0, r1);
            pk.y = pack_f16x2(r2, r3);
            pk.z = pack_f16x2(r4, r5);
            pk.w = pack_f16x2(r6, r7);
            *(uint4*)(tb + j * TSTR + ko) = pk;
        }
    }
    __syncthreads();

    #pragma unroll
    for (int jt = 0; jt < 4; ++jt) {
        int jbase = jt << 7;
        uint32_t Tcur = (jt & 1) ? Tb1 : Tb0;

        #pragma unroll
        for (int s = 0; s < 2; ++s) {
            float acc[4][4];
            #pragma unroll
            for (int nt = 0; nt < 4; ++nt) {
                acc[nt][0] = 0.f; acc[nt][1] = 0.f; acc[nt][2] = 0.f; acc[nt][3] = 0.f;
            }
            #pragma unroll
            for (int k = 0; k < 4; ++k) {
                uint32_t a0, a1, a2, a3;
                uint32_t a_addr = Tcur + (uint32_t)(((mq * 32 + s * 16 + a_row) * TSTR
                                                    + k * 16 + a_kh * 8) * 2);
                ldsm_x4(a0, a1, a2, a3, a_addr);
                #pragma unroll
                for (int nt = 0; nt < 4; ++nt)
                    mma16816(acc[nt][0], acc[nt][1], acc[nt][2], acc[nt][3],
                             a0, a1, a2, a3, Bfr[k][nt][0], Bfr[k][nt][1]);
            }
            int r = jbase + mq * 32 + s * 16 + (lane >> 2);
            float aj0 = adjrow[r];
            float aj1 = adjrow[r + 8];
            #pragma unroll
            for (int nt = 0; nt < 4; ++nt) {
                int h0 = nq * 32 + nt * 8 + (lane & 3) * 2;
                float bb0 = sb2[h0];
                float bb1 = sb2[h0 + 1];
                sacc[nt * 2 + 0] += aj0 * fmaxf(acc[nt][0] + bb0, 0.f)
                                  + aj1 * fmaxf(acc[nt][2] + bb0, 0.f);
                sacc[nt * 2 + 1] += aj0 * fmaxf(acc[nt][1] + bb1, 0.f)
                                  + aj1 * fmaxf(acc[nt][3] + bb1, 0.f);
            }
        }

        if (jt < 3) {
            __half* tb = (jt & 1) ? Tsh[0] : Tsh[1];
            int jb = jbase + 128;
            #pragma unroll
            for (int jj = 0; jj < 4; ++jj) {
                int j = jrow4 + jj;
                float x0 = sx[(jb + j) * 2 + 0];
                float x1 = sx[(jb + j) * 2 + 1];
                uint4 pk;
                float r0 = fmaxf(fmaf(w3r[0], x1, fmaf(w2r[0], x0, ur[0])), 0.f);
                float r1 = fmaxf(fmaf(w3r[1], x1, fmaf(w2r[1], x0, ur[1])), 0.f);
                float r2 = fmaxf(fmaf(w3r[2], x1, fmaf(w2r[2], x0, ur[2])), 0.f);
                float r3 = fmaxf(fmaf(w3r[3], x1, fmaf(w2r[3], x0, ur[3])), 0.f);
                float r4 = fmaxf(fmaf(w3r[4], x1, fmaf(w2r[4], x0, ur[4])), 0.f);
                float r5 = fmaxf(fmaf(w3r[5], x1, fmaf(w2r[5], x0, ur[5])), 0.f);
                float r6 = fmaxf(fmaf(w3r[6], x1, fmaf(w2r[6], x0, ur[6])), 0.f);
                float r7 = fmaxf(fmaf(w3r[7], x1, fmaf(w2r[7], x0, ur[7])), 0.f);
                pk.x = pack_f16x2(r0, r1);
                pk.y = pack_f16x2(r2, r3);
                pk.z = pack_f16x2(r4, r5);
                pk.w = pack_f16x2(r6, r7);
                *(uint4*)(tb + j * TSTR + ko) = pk;
            }
        }
        __syncthreads();
    }

    // ---- reduce s over warps ----
    #pragma unroll
    for (int q = 0; q < 8; ++q) {
        sacc[q] += __shfl_down_sync(0xFFFFFFFFu, sacc[q], 16);
        sacc[q] += __shfl_down_sync(0xFFFFFFFFu, sacc[q], 8);
        sacc[q] += __shfl_down_sync(0xFFFFFFFFu, sacc[q], 4);
    }
    if (lane < 4) {
        #pragma unroll
        for (int nt = 0; nt < 4; ++nt) {
            red[w][nt * 8 + lane * 2 + 0] = sacc[nt * 2 + 0];
            red[w][nt * 8 + lane * 2 + 1] = sacc[nt * 2 + 1];
        }
    }
    __syncthreads();
    if (t < 64) {
        int nq2 = t >> 5;
        int hh = t & 31;
        sfin[t] = red[nq2 * 4 + 0][hh] + red[nq2 * 4 + 1][hh]
                + red[nq2 * 4 + 2][hh] + red[nq2 * 4 + 3][hh];
    }
    __syncthreads();

    // ================== fused node head ==================
    int h = t & 63;
    int q = t >> 6;            // partial-k group: k in [16q, 16q+16)

    // ---- layer 1: h1 = relu(We2n @ s + b) ----
    {
        const float* wrow = We2n + h * 64 + q * 16;
        const float* sv = sfin + q * 16;
        float a = 0.f;
        #pragma unroll
        for (int c = 0; c < 4; ++c) {
            float4 f = *(const float4*)(wrow + c * 4);
            a += f.x * sv[c * 4 + 0] + f.y * sv[c * 4 + 1]
               + f.z * sv[c * 4 + 2] + f.w * sv[c * 4 + 3];
        }
        part[q * 64 + h] = a;
    }
    __syncthreads();
    if (t < 64) hA[t] = fmaxf(be2n[t] + part[t] + part[64 + t] + part[128 + t] + part[192 + t], 0.f);
    __syncthreads();

    // ---- layer 2: h2 = relu(Wn2n @ h1 + b) ----
    {
        const float* wrow = Wn2n + h * 64 + q * 16;
        const float* sv = hA + q * 16;
        float a = 0.f;
        #pragma unroll
        for (int c = 0; c < 4; ++c) {
            float4 f = *(const float4*)(wrow + c * 4);
            a += f.x * sv[c * 4 + 0] + f.y * sv[c * 4 + 1]
               + f.z * sv[c * 4 + 2] + f.w * sv[c * 4 + 3];
        }
        part[q * 64 + h] = a;
    }
    __syncthreads();
    if (t < 64) hB[t] = fmaxf(bn2n[t] + part[t] + part[64 + t] + part[128 + t] + part[192 + t], 0.f);
    __syncthreads();

    // ---- layer 3: h3 = relu(Wo1 @ cat(x_i, h2) + b), Wo1 is [64][66] ----
    {
        const float* wrow = Wo1 + h * 66 + 2 + q * 16;   // h2 portion
        const float* sv = hB + q * 16;
        float a = 0.f;
        #pragma unroll
        for (int c = 0; c < 4; ++c) {
            float fx = wrow[c * 4 + 0], fy = wrow[c * 4 + 1];
            float fz = wrow[c * 4 + 2], fw = wrow[c * 4 + 3];
            a += fx * sv[c * 4 + 0] + fy * sv[c * 4 + 1]
               + fz * sv[c * 4 + 2] + fw * sv[c * 4 + 3];
        }
        if (q == 0) {
            float xi0 = sx[i * 2 + 0];
            float xi1 = sx[i * 2 + 1];
            a += Wo1[h * 66 + 0] * xi0 + Wo1[h * 66 + 1] * xi1;
        }
        part[q * 64 + h] = a;
    }
    __syncthreads();
    if (t < 64) hA[t] = fmaxf(bo1[t] + part[t] + part[64 + t] + part[128 + t] + part[192 + t], 0.f);
    __syncthreads();

    // ---- output: out = Wo2 @ h3 + b, [2][64] ----
    if (t < 128) {
        int o = t >> 6;
        int k = t & 63;
        float p = Wo2[o * 64 + k] * hA[k];
        p += __shfl_down_sync(0xFFFFFFFFu, p, 16);
        p += __shfl_down_sync(0xFFFFFFFFu, p, 8);
        p += __shfl_down_sync(0xFFFFFFFFu, p, 4);
        p += __shfl_down_sync(0xFFFFFFFFu, p, 2);
        p += __shfl_down_sync(0xFFFFFFFFu, p, 1);
        if ((t & 31) == 0) part[t >> 5] = p;   // [o0w0, o0w1, o1w0, o1w1]
    }
    __syncthreads();
    if (t < 2) out[bi * 2 + t] = bo2[t] + part[t * 2 + 0] + part[t * 2 + 1];
}

// ---------------------------------------------------------------------------
extern "C" void kernel_launch(void* const* d_in, const int* in_sizes, int n_in,
                              void* d_out, int out_size) {
    const float* input = (const float*)d_in[0];
    const float* adj   = (const float*)d_in[1];
    const float* W_n2e = (const float*)d_in[2];
    const float* b_n2e = (const float*)d_in[3];
    const float* W_e2e = (const float*)d_in[4];
    const float* b_e2e = (const float*)d_in[5];
    const float* W_e2n = (const float*)d_in[6];
    const float* b_e2n = (const float*)d_in[7];
    const float* W_n2n = (const float*)d_in[8];
    const float* b_n2n = (const float*)d_in[9];
    const float* W_o1  = (const float*)d_in[10];
    const float* b_o1  = (const float*)d_in[11];
    const float* W_o2  = (const float*)d_in[12];
    const float* b_o2  = (const float*)d_in[13];
    float* out = (float*)d_out;

    k_fused<<<NB * NN, 256>>>(input, adj, W_n2e, b_n2e, W_e2e, b_e2e,
                              W_e2n, b_e2n, W_n2n, b_n2n,
                              W_o1, b_o1, W_o2, b_o2, out);
}

// round 10
// speedup vs baseline: 1.1466x; 1.1466x over previous
#include <cuda_runtime.h>
#include <cuda_fp16.h>
#include <cstdint>

// Shapes (fixed)
#define NB 4
#define NN 512
#define ND 2
#define NH 64
#define NO 2

// Scratch
__device__ float g_s[NB * NN * NH];

// ---------------------------------------------------------------------------
__device__ __forceinline__ uint32_t smem_u32(const void* p) {
    uint32_t a;
    asm("{ .reg .u64 t; cvta.to.shared.u64 t, %1; cvt.u32.u64 %0, t; }" : "=r"(a) : "l"(p));
    return a;
}
__device__ __forceinline__ uint32_t pack_f16x2(float a, float b) {
    uint32_t r;
    asm("cvt.rn.f16x2.f32 %0, %2, %1;" : "=r"(r) : "f"(a), "f"(b));
    return r;
}
__device__ __forceinline__ void ldsm_x4(uint32_t& a0, uint32_t& a1, uint32_t& a2,
                                        uint32_t& a3, uint32_t addr) {
    asm volatile("ldmatrix.sync.aligned.m8n8.x4.shared.b16 {%0,%1,%2,%3}, [%4];"
                 : "=r"(a0), "=r"(a1), "=r"(a2), "=r"(a3) : "r"(addr));
}
__device__ __forceinline__ void ldsm_x2(uint32_t& b0, uint32_t& b1, uint32_t addr) {
    asm volatile("ldmatrix.sync.aligned.m8n8.x2.shared.b16 {%0,%1}, [%2];"
                 : "=r"(b0), "=r"(b1) : "r"(addr));
}
__device__ __forceinline__ void mma16816(float& c0, float& c1, float& c2, float& c3,
                                         uint32_t a0, uint32_t a1, uint32_t a2, uint32_t a3,
                                         uint32_t b0, uint32_t b1) {
    asm volatile("mma.sync.aligned.m16n8k16.row.col.f32.f16.f16.f32 "
                 "{%0,%1,%2,%3}, {%4,%5,%6,%7}, {%8,%9}, {%0,%1,%2,%3};"
                 : "+f"(c0), "+f"(c1), "+f"(c2), "+f"(c3)
                 : "r"(a0), "r"(a1), "r"(a2), "r"(a3), "r"(b0), "r"(b1));
}

#define TSTR 72
#define WSTR 72

// ---------------------------------------------------------------------------
// Edge kernel (unchanged from R8): one CTA per (b,i), 256 thr, HMMA GEMM,
// v recomputed from x (no LDG in mainloop), fused relu(+b2)*adj epilogue.
// ---------------------------------------------------------------------------
__global__ void __launch_bounds__(256, 2) k_edge_mma(const float* __restrict__ x,
                                                     const float* __restrict__ adj,
                                                     const float* __restrict__ Wn2e,
                                                     const float* __restrict__ bn2e,
                                                     const float* __restrict__ We2e,
                                                     const float* __restrict__ be2e) {
    __shared__ __align__(16) __half Tsh[2][128 * TSTR];
    __shared__ __align__(16) char wpool[64 * WSTR * 2];   // Wsh then sx
    __shared__ float su[64];
    __shared__ float sb2[64];
    __shared__ float red[8][32];

    __half* Wsh = (__half*)wpool;
    float* sx = (float*)wpool;      // [512][2] after hoist

    int t = threadIdx.x;
    int w = t >> 5;
    int lane = t & 31;
    int bi = blockIdx.x;
    int b = bi >> 9;
    int i = bi & 511;
    int mq = w & 3;
    int nq = w >> 2;

    uint32_t Tb0 = smem_u32(Tsh[0]);
    uint32_t Tb1 = smem_u32(Tsh[1]);
    uint32_t Wb = smem_u32(wpool);

    {
        int h = t >> 2;
        int kb = (t & 3) * 16;
        const float* wrow = We2e + h * 64 + kb;
        #pragma unroll
        for (int c = 0; c < 2; ++c) {
            float4 f0 = *(const float4*)(wrow + c * 8);
            float4 f1 = *(const float4*)(wrow + c * 8 + 4);
            uint4 pk;
            pk.x = pack_f16x2(f0.x, f0.y);
            pk.y = pack_f16x2(f0.z, f0.w);
            pk.z = pack_f16x2(f1.x, f1.y);
            pk.w = pack_f16x2(f1.z, f1.w);
            *(uint4*)(Wsh + h * WSTR + kb + c * 8) = pk;
        }
    }
    if (t < 64) {
        float4 wr = *(const float4*)(Wn2e + t * 4);
        float xi0 = x[(b * NN + i) * 2 + 0];
        float xi1 = x[(b * NN + i) * 2 + 1];
        su[t]  = bn2e[t] + wr.x * xi0 + wr.y * xi1;
        sb2[t] = be2e[t];
    }
    __syncthreads();

    uint32_t Bfr[4][4][2];
    #pragma unroll
    for (int k = 0; k < 4; ++k) {
        #pragma unroll
        for (int nt = 0; nt < 4; ++nt) {
            uint32_t addr = Wb + (uint32_t)(((nq * 32 + nt * 8 + (lane & 7)) * WSTR
                                             + k * 16 + ((lane >> 3) & 1) * 8) * 2);
            ldsm_x2(Bfr[k][nt][0], Bfr[k][nt][1], addr);
        }
    }
    __syncthreads();

    {
        const float* xb = x + b * NN * 2;
        for (int idx = t; idx < NN * 2 / 4; idx += 256)
            ((float4*)sx)[idx] = ((const float4*)xb)[idx];
    }

    int ko = (t & 7) * 8;
    int jrow4 = (t >> 3) * 4;
    float w2r[8], w3r[8], ur[8];
    #pragma unroll
    for (int kk = 0; kk < 8; ++kk) {
        float4 wr = *(const float4*)(Wn2e + (ko + kk) * 4);
        w2r[kk] = wr.z;
        w3r[kk] = wr.w;
    }
    __syncthreads();
    #pragma unroll
    for (int kk = 0; kk < 8; ++kk) ur[kk] = su[ko + kk];

    const float* adjrow = adj + i * NN;

    float sacc[8];
    #pragma unroll
    for (int q = 0; q < 8; ++q) sacc[q] = 0.f;

    int a_row = lane & 15;
    int a_kh = lane >> 4;

    {
        __half* tb = Tsh[0];
        #pragma unroll
        for (int jj = 0; jj < 4; ++jj) {
            int j = jrow4 + jj;
            float x0 = sx[j * 2 + 0];
            float x1 = sx[j * 2 + 1];
            uint4 pk;
            float r0 = fmaxf(fmaf(w3r[0], x1, fmaf(w2r[0], x0, ur[0])), 0.f);
            float r1 = fmaxf(fmaf(w3r[1], x1, fmaf(w2r[1], x0, ur[1])), 0.f);
            float r2 = fmaxf(fmaf(w3r[2], x1, fmaf(w2r[2], x0, ur[2])), 0.f);
            float r3 = fmaxf(fmaf(w3r[3], x1, fmaf(w2r[3], x0, ur[3])), 0.f);
            float r4 = fmaxf(fmaf(w3r[4], x1, fmaf(w2r[4], x0, ur[4])), 0.f);
            float r5 = fmaxf(fmaf(w3r[5], x1, fmaf(w2r[5], x0, ur[5])), 0.f);
            float r6 = fmaxf(fmaf(w3r[6], x1, fmaf(w2r[6], x0, ur[6])), 0.f);
            float r7 = fmaxf(fmaf(w3r[7], x1, fmaf(w2r[7], x0, ur[7])), 0.f);
            pk.x = pack_f16x2(r0, r1);
            pk.y = pack_f16x2(r2, r3);
            pk.z = pack_f16x2(r4, r5);
            pk.w = pack_f16x2(r6, r7);
            *(uint4*)(tb + j * TSTR + ko) = pk;
        }
    }
    __syncthreads();

    #pragma unroll
    for (int jt = 0; jt < 4; ++jt) {
        int jbase = jt << 7;
        uint32_t Tcur = (jt & 1) ? Tb1 : Tb0;

        #pragma unroll
        for (int s = 0; s < 2; ++s) {
            float acc[4][4];
            #pragma unroll
            for (int nt = 0; nt < 4; ++nt) {
                acc[nt][0] = 0.f; acc[nt][1] = 0.f; acc[nt][2] = 0.f; acc[nt][3] = 0.f;
            }
            #pragma unroll
            for (int k = 0; k < 4; ++k) {
                uint32_t a0, a1, a2, a3;
                uint32_t a_addr = Tcur + (uint32_t)(((mq * 32 + s * 16 + a_row) * TSTR
                                                    + k * 16 + a_kh * 8) * 2);
                ldsm_x4(a0, a1, a2, a3, a_addr);
                #pragma unroll
                for (int nt = 0; nt < 4; ++nt)
                    mma16816(acc[nt][0], acc[nt][1], acc[nt][2], acc[nt][3],
                             a0, a1, a2, a3, Bfr[k][nt][0], Bfr[k][nt][1]);
            }
            int r = jbase + mq * 32 + s * 16 + (lane >> 2);
            float aj0 = adjrow[r];
            float aj1 = adjrow[r + 8];
            #pragma unroll
            for (int nt = 0; nt < 4; ++nt) {
                int h0 = nq * 32 + nt * 8 + (lane & 3) * 2;
                float bb0 = sb2[h0];
                float bb1 = sb2[h0 + 1];
                sacc[nt * 2 + 0] += aj0 * fmaxf(acc[nt][0] + bb0, 0.f)
                                  + aj1 * fmaxf(acc[nt][2] + bb0, 0.f);
                sacc[nt * 2 + 1] += aj0 * fmaxf(acc[nt][1] + bb1, 0.f)
                                  + aj1 * fmaxf(acc[nt][3] + bb1, 0.f);
            }
        }

        if (jt < 3) {
            __half* tb = (jt & 1) ? Tsh[0] : Tsh[1];
            int jb = jbase + 128;
            #pragma unroll
            for (int jj = 0; jj < 4; ++jj) {
                int j = jrow4 + jj;
                float x0 = sx[(jb + j) * 2 + 0];
                float x1 = sx[(jb + j) * 2 + 1];
                uint4 pk;
                float r0 = fmaxf(fmaf(w3r[0], x1, fmaf(w2r[0], x0, ur[0])), 0.f);
                float r1 = fmaxf(fmaf(w3r[1], x1, fmaf(w2r[1], x0, ur[1])), 0.f);
                float r2 = fmaxf(fmaf(w3r[2], x1, fmaf(w2r[2], x0, ur[2])), 0.f);
                float r3 = fmaxf(fmaf(w3r[3], x1, fmaf(w2r[3], x0, ur[3])), 0.f);
                float r4 = fmaxf(fmaf(w3r[4], x1, fmaf(w2r[4], x0, ur[4])), 0.f);
                float r5 = fmaxf(fmaf(w3r[5], x1, fmaf(w2r[5], x0, ur[5])), 0.f);
                float r6 = fmaxf(fmaf(w3r[6], x1, fmaf(w2r[6], x0, ur[6])), 0.f);
                float r7 = fmaxf(fmaf(w3r[7], x1, fmaf(w2r[7], x0, ur[7])), 0.f);
                pk.x = pack_f16x2(r0, r1);
                pk.y = pack_f16x2(r2, r3);
                pk.z = pack_f16x2(r4, r5);
                pk.w = pack_f16x2(r6, r7);
                *(uint4*)(tb + j * TSTR + ko) = pk;
            }
        }
        __syncthreads();
    }

    #pragma unroll
    for (int q = 0; q < 8; ++q) {
        sacc[q] += __shfl_down_sync(0xFFFFFFFFu, sacc[q], 16);
        sacc[q] += __shfl_down_sync(0xFFFFFFFFu, sacc[q], 8);
        sacc[q] += __shfl_down_sync(0xFFFFFFFFu, sacc[q], 4);
    }
    if (lane < 4) {
        #pragma unroll
        for (int nt = 0; nt < 4; ++nt) {
            red[w][nt * 8 + lane * 2 + 0] = sacc[nt * 2 + 0];
            red[w][nt * 8 + lane * 2 + 1] = sacc[nt * 2 + 1];
        }
    }
    __syncthreads();
    if (t < 64) {
        int nq2 = t >> 5;
        int hh = t & 31;
        g_s[bi * 64 + t] = red[nq2 * 4 + 0][hh] + red[nq2 * 4 + 1][hh]
                         + red[nq2 * 4 + 2][hh] + red[nq2 * 4 + 3][hh];
    }
}

// ---------------------------------------------------------------------------
// Head kernel: 256 CTAs x 8 nodes, 256 thr. Weights staged transposed with
// pad-65 (conflict-free staging AND gemv reads). Inputs broadcast via SMEM.
// ---------------------------------------------------------------------------
__global__ void __launch_bounds__(256) k_head(const float* __restrict__ x,
                                              const float* __restrict__ We2n,
                                              const float* __restrict__ be2n,
                                              const float* __restrict__ Wn2n,
                                              const float* __restrict__ bn2n,
                                              const float* __restrict__ Wo1,
                                              const float* __restrict__ bo1,
                                              const float* __restrict__ Wo2,
                                              const float* __restrict__ bo2,
                                              float* __restrict__ out) {
    __shared__ float wbuf[66 * 65];      // transposed, pad-65: wbuf[c*65 + h]
    __shared__ float bufA[8][64];
    __shared__ float bufB[8][64];
    __shared__ float sxl[8][2];

    int t = threadIdx.x;
    int h = t & 63;
    int g = t >> 6;              // 4 k-groups -> node pairs
    int nbase = blockIdx.x * 8;

    // stage s and x
    {
        int idx = t;             // 512 = 8 nodes * 64
        bufA[idx >> 6][idx & 63] = g_s[(nbase + (idx >> 6)) * 64 + (idx & 63)];
        idx = t + 256;
        bufA[idx >> 6][idx & 63] = g_s[(nbase + (idx >> 6)) * 64 + (idx & 63)];
    }
    if (t < 16) sxl[t >> 1][t & 1] = x[(nbase + (t >> 1)) * 2 + (t & 1)];

    // ---- layer 1 ----
    for (int idx = t; idx < 64 * 64; idx += 256)
        wbuf[(idx & 63) * 65 + (idx >> 6)] = We2n[idx];   // wbuf[k*65+h] = W[h][k]
    __syncthreads();
    {
        float bh = be2n[h];
        #pragma unroll
        for (int p = 0; p < 2; ++p) {
            int n = g * 2 + p;
            float acc = bh;
            #pragma unroll 16
            for (int k = 0; k < 64; ++k) acc += wbuf[k * 65 + h] * bufA[n][k];
            bufB[n][h] = fmaxf(acc, 0.f);
        }
    }
    __syncthreads();

    // ---- layer 2 ----
    for (int idx = t; idx < 64 * 64; idx += 256)
        wbuf[(idx & 63) * 65 + (idx >> 6)] = Wn2n[idx];
    __syncthreads();
    {
        float bh = bn2n[h];
        #pragma unroll
        for (int p = 0; p < 2; ++p) {
            int n = g * 2 + p;
            float acc = bh;
            #pragma unroll 16
            for (int k = 0; k < 64; ++k) acc += wbuf[k * 65 + h] * bufB[n][k];
            bufA[n][h] = fmaxf(acc, 0.f);
        }
    }
    __syncthreads();

    // ---- layer 3: Wo1 [64][66], input = cat(x, h2) ----
    for (int idx = t; idx < 64 * 66; idx += 256) {
        int hh = idx / 66;
        int c = idx % 66;
        wbuf[c * 65 + hh] = Wo1[idx];
    }
    __syncthreads();
    {
        float bh = bo1[h];
        #pragma unroll
        for (int p = 0; p < 2; ++p) {
            int n = g * 2 + p;
            float acc = bh + wbuf[0 * 65 + h] * sxl[n][0]
                          + wbuf[1 * 65 + h] * sxl[n][1];
            #pragma unroll 16
            for (int k = 0; k < 64; ++k) acc += wbuf[(k + 2) * 65 + h] * bufA[n][k];
            bufB[n][h] = fmaxf(acc, 0.f);
        }
    }
    __syncthreads();

    // ---- output: warp per node, both o via lane-split dot ----
    {
        int n = t >> 5;          // 0..7
        int lane = t & 31;
        #pragma unroll
        for (int o = 0; o < 2; ++o) {
            float p = Wo2[o * 64 + lane] * bufB[n][lane]
                    + Wo2[o * 64 + 32 + lane] * bufB[n][32 + lane];
            p += __shfl_down_sync(0xFFFFFFFFu, p, 16);
            p += __shfl_down_sync(0xFFFFFFFFu, p, 8);
            p += __shfl_down_sync(0xFFFFFFFFu, p, 4);
            p += __shfl_down_sync(0xFFFFFFFFu, p, 2);
            p += __shfl_down_sync(0xFFFFFFFFu, p, 1);
            if (lane == 0) out[(nbase + n) * 2 + o] = bo2[o] + p;
        }
    }
}

// ---------------------------------------------------------------------------
extern "C" void kernel_launch(void* const* d_in, const int* in_sizes, int n_in,
                              void* d_out, int out_size) {
    const float* input = (const float*)d_in[0];
    const float* adj   = (const float*)d_in[1];
    const float* W_n2e = (const float*)d_in[2];
    const float* b_n2e = (const float*)d_in[3];
    const float* W_e2e = (const float*)d_in[4];
    const float* b_e2e = (const float*)d_in[5];
    const float* W_e2n = (const float*)d_in[6];
    const float* b_e2n = (const float*)d_in[7];
    const float* W_n2n = (const float*)d_in[8];
    const float* b_n2n = (const float*)d_in[9];
    const float* W_o1  = (const float*)d_in[10];
    const float* b_o1  = (const float*)d_in[11];
    const float* W_o2  = (const float*)d_in[12];
    const float* b_o2  = (const float*)d_in[13];
    float* out = (float*)d_out;

    k_edge_mma<<<NB * NN, 256>>>(input, adj, W_n2e, b_n2e, W_e2e, b_e2e);
    k_head<<<NB * NN / 8, 256>>>(input, W_e2n, b_e2n, W_n2n, b_n2n,
                                 W_o1, b_o1, W_o2, b_o2, out);
}

// round 11
// speedup vs baseline: 1.2988x; 1.1327x over previous
#include <cuda_runtime.h>
#include <cuda_fp16.h>
#include <cstdint>

// Shapes (fixed)
#define NB 4
#define NN 512
#define ND 2
#define NH 64
#define NO 2

// Scratch
__device__ float g_s[NB * NN * NH];

// ---------------------------------------------------------------------------
__device__ __forceinline__ uint32_t smem_u32(const void* p) {
    uint32_t a;
    asm("{ .reg .u64 t; cvta.to.shared.u64 t, %1; cvt.u32.u64 %0, t; }" : "=r"(a) : "l"(p));
    return a;
}
__device__ __forceinline__ uint32_t pack_f16x2(float a, float b) {
    uint32_t r;
    asm("cvt.rn.f16x2.f32 %0, %2, %1;" : "=r"(r) : "f"(a), "f"(b));
    return r;
}
__device__ __forceinline__ uint32_t h2u(__half2 v) {
    return *reinterpret_cast<uint32_t*>(&v);
}
__device__ __forceinline__ void ldsm_x4(uint32_t& a0, uint32_t& a1, uint32_t& a2,
                                        uint32_t& a3, uint32_t addr) {
    asm volatile("ldmatrix.sync.aligned.m8n8.x4.shared.b16 {%0,%1,%2,%3}, [%4];"
                 : "=r"(a0), "=r"(a1), "=r"(a2), "=r"(a3) : "r"(addr));
}
__device__ __forceinline__ void ldsm_x2(uint32_t& b0, uint32_t& b1, uint32_t addr) {
    asm volatile("ldmatrix.sync.aligned.m8n8.x2.shared.b16 {%0,%1}, [%2];"
                 : "=r"(b0), "=r"(b1) : "r"(addr));
}
__device__ __forceinline__ void mma16816(float& c0, float& c1, float& c2, float& c3,
                                         uint32_t a0, uint32_t a1, uint32_t a2, uint32_t a3,
                                         uint32_t b0, uint32_t b1) {
    asm volatile("mma.sync.aligned.m16n8k16.row.col.f32.f16.f16.f32 "
                 "{%0,%1,%2,%3}, {%4,%5,%6,%7}, {%8,%9}, {%0,%1,%2,%3};"
                 : "+f"(c0), "+f"(c1), "+f"(c2), "+f"(c3)
                 : "r"(a0), "r"(a1), "r"(a2), "r"(a3), "r"(b0), "r"(b1));
}

#define TSTR 72
#define WSTR 72

// ---------------------------------------------------------------------------
// Edge kernel: one CTA per (b,i), 256 thr, HMMA GEMM, T built in packed HFMA2
// (no LDG in mainloop), fused relu(+b2)*adj epilogue -> g_s.
// ---------------------------------------------------------------------------
__global__ void __launch_bounds__(256, 2) k_edge_mma(const float* __restrict__ x,
                                                     const float* __restrict__ adj,
                                                     const float* __restrict__ Wn2e,
                                                     const float* __restrict__ bn2e,
                                                     const float* __restrict__ We2e,
                                                     const float* __restrict__ be2e) {
    __shared__ __align__(16) __half Tsh[2][128 * TSTR];
    __shared__ __align__(16) char wpool[64 * WSTR * 2];   // Wsh then sx
    __shared__ float su[64];
    __shared__ float sb2[64];
    __shared__ float red[8][32];

    __half* Wsh = (__half*)wpool;
    float* sx = (float*)wpool;      // [512][2] after hoist

    int t = threadIdx.x;
    int w = t >> 5;
    int lane = t & 31;
    int bi = blockIdx.x;
    int b = bi >> 9;
    int i = bi & 511;
    int mq = w & 3;
    int nq = w >> 2;

    uint32_t Tb0 = smem_u32(Tsh[0]);
    uint32_t Tb1 = smem_u32(Tsh[1]);
    uint32_t Wb = smem_u32(wpool);

    {
        int h = t >> 2;
        int kb = (t & 3) * 16;
        const float* wrow = We2e + h * 64 + kb;
        #pragma unroll
        for (int c = 0; c < 2; ++c) {
            float4 f0 = *(const float4*)(wrow + c * 8);
            float4 f1 = *(const float4*)(wrow + c * 8 + 4);
            uint4 pk;
            pk.x = pack_f16x2(f0.x, f0.y);
            pk.y = pack_f16x2(f0.z, f0.w);
            pk.z = pack_f16x2(f1.x, f1.y);
            pk.w = pack_f16x2(f1.z, f1.w);
            *(uint4*)(Wsh + h * WSTR + kb + c * 8) = pk;
        }
    }
    if (t < 64) {
        float4 wr = *(const float4*)(Wn2e + t * 4);
        float xi0 = x[(b * NN + i) * 2 + 0];
        float xi1 = x[(b * NN + i) * 2 + 1];
        su[t]  = bn2e[t] + wr.x * xi0 + wr.y * xi1;
        sb2[t] = be2e[t];
    }
    __syncthreads();

    uint32_t Bfr[4][4][2];
    #pragma unroll
    for (int k = 0; k < 4; ++k) {
        #pragma unroll
        for (int nt = 0; nt < 4; ++nt) {
            uint32_t addr = Wb + (uint32_t)(((nq * 32 + nt * 8 + (lane & 7)) * WSTR
                                             + k * 16 + ((lane >> 3) & 1) * 8) * 2);
            ldsm_x2(Bfr[k][nt][0], Bfr[k][nt][1], addr);
        }
    }
    __syncthreads();

    {
        const float* xb = x + b * NN * 2;
        for (int idx = t; idx < NN * 2 / 4; idx += 256)
            ((float4*)sx)[idx] = ((const float4*)xb)[idx];
    }

    // per-thread k-octet constants as packed half2
    int ko = (t & 7) * 8;
    int jrow4 = (t >> 3) * 4;
    __half2 w2h[4], w3h[4], uh[4];
    #pragma unroll
    for (int c = 0; c < 4; ++c) {
        float4 wr0 = *(const float4*)(Wn2e + (ko + 2 * c) * 4);
        float4 wr1 = *(const float4*)(Wn2e + (ko + 2 * c + 1) * 4);
        w2h[c] = __floats2half2_rn(wr0.z, wr1.z);
        w3h[c] = __floats2half2_rn(wr0.w, wr1.w);
    }
    __syncthreads();
    #pragma unroll
    for (int c = 0; c < 4; ++c)
        uh[c] = __floats2half2_rn(su[ko + 2 * c], su[ko + 2 * c + 1]);

    const float* adjrow = adj + i * NN;
    const __half2 z2 = __float2half2_rn(0.f);

    float sacc[8];
    #pragma unroll
    for (int q = 0; q < 8; ++q) sacc[q] = 0.f;

    int a_row = lane & 15;
    int a_kh = lane >> 4;

    // ---- build tile 0 (HFMA2) ----
    {
        __half* tb = Tsh[0];
        #pragma unroll
        for (int jj = 0; jj < 4; ++jj) {
            int j = jrow4 + jj;
            __half2 x0h = __float2half2_rn(sx[j * 2 + 0]);
            __half2 x1h = __float2half2_rn(sx[j * 2 + 1]);
            __half2 t0 = __hmax2(__hfma2(w3h[0], x1h, __hfma2(w2h[0], x0h, uh[0])), z2);
            __half2 t1 = __hmax2(__hfma2(w3h[1], x1h, __hfma2(w2h[1], x0h, uh[1])), z2);
            __half2 t2 = __hmax2(__hfma2(w3h[2], x1h, __hfma2(w2h[2], x0h, uh[2])), z2);
            __half2 t3 = __hmax2(__hfma2(w3h[3], x1h, __hfma2(w2h[3], x0h, uh[3])), z2);
            uint4 pk = make_uint4(h2u(t0), h2u(t1), h2u(t2), h2u(t3));
            *(uint4*)(tb + j * TSTR + ko) = pk;
        }
    }
    __syncthreads();

    #pragma unroll
    for (int jt = 0; jt < 4; ++jt) {
        int jbase = jt << 7;
        uint32_t Tcur = (jt & 1) ? Tb1 : Tb0;

        #pragma unroll
        for (int s = 0; s < 2; ++s) {
            float acc[4][4];
            #pragma unroll
            for (int nt = 0; nt < 4; ++nt) {
                acc[nt][0] = 0.f; acc[nt][1] = 0.f; acc[nt][2] = 0.f; acc[nt][3] = 0.f;
            }
            #pragma unroll
            for (int k = 0; k < 4; ++k) {
                uint32_t a0, a1, a2, a3;
                uint32_t a_addr = Tcur + (uint32_t)(((mq * 32 + s * 16 + a_row) * TSTR
                                                    + k * 16 + a_kh * 8) * 2);
                ldsm_x4(a0, a1, a2, a3, a_addr);
                #pragma unroll
                for (int nt = 0; nt < 4; ++nt)
                    mma16816(acc[nt][0], acc[nt][1], acc[nt][2], acc[nt][3],
                             a0, a1, a2, a3, Bfr[k][nt][0], Bfr[k][nt][1]);
            }
            int r = jbase + mq * 32 + s * 16 + (lane >> 2);
            float aj0 = adjrow[r];
            float aj1 = adjrow[r + 8];
            #pragma unroll
            for (int nt = 0; nt < 4; ++nt) {
                int h0 = nq * 32 + nt * 8 + (lane & 3) * 2;
                float bb0 = sb2[h0];
                float bb1 = sb2[h0 + 1];
                sacc[nt * 2 + 0] += aj0 * fmaxf(acc[nt][0] + bb0, 0.f)
                                  + aj1 * fmaxf(acc[nt][2] + bb0, 0.f);
                sacc[nt * 2 + 1] += aj0 * fmaxf(acc[nt][1] + bb1, 0.f)
                                  + aj1 * fmaxf(acc[nt][3] + bb1, 0.f);
            }
        }

        if (jt < 3) {
            __half* tb = (jt & 1) ? Tsh[0] : Tsh[1];
            int jb = jbase + 128;
            #pragma unroll
            for (int jj = 0; jj < 4; ++jj) {
                int j = jrow4 + jj;
                __half2 x0h = __float2half2_rn(sx[(jb + j) * 2 + 0]);
                __half2 x1h = __float2half2_rn(sx[(jb + j) * 2 + 1]);
                __half2 t0 = __hmax2(__hfma2(w3h[0], x1h, __hfma2(w2h[0], x0h, uh[0])), z2);
                __half2 t1 = __hmax2(__hfma2(w3h[1], x1h, __hfma2(w2h[1], x0h, uh[1])), z2);
                __half2 t2 = __hmax2(__hfma2(w3h[2], x1h, __hfma2(w2h[2], x0h, uh[2])), z2);
                __half2 t3 = __hmax2(__hfma2(w3h[3], x1h, __hfma2(w2h[3], x0h, uh[3])), z2);
                uint4 pk = make_uint4(h2u(t0), h2u(t1), h2u(t2), h2u(t3));
                *(uint4*)(tb + j * TSTR + ko) = pk;
            }
        }
        __syncthreads();
    }

    #pragma unroll
    for (int q = 0; q < 8; ++q) {
        sacc[q] += __shfl_down_sync(0xFFFFFFFFu, sacc[q], 16);
        sacc[q] += __shfl_down_sync(0xFFFFFFFFu, sacc[q], 8);
        sacc[q] += __shfl_down_sync(0xFFFFFFFFu, sacc[q], 4);
    }
    if (lane < 4) {
        #pragma unroll
        for (int nt = 0; nt < 4; ++nt) {
            red[w][nt * 8 + lane * 2 + 0] = sacc[nt * 2 + 0];
            red[w][nt * 8 + lane * 2 + 1] = sacc[nt * 2 + 1];
        }
    }
    __syncthreads();
    if (t < 64) {
        int nq2 = t >> 5;
        int hh = t & 31;
        g_s[bi * 64 + t] = red[nq2 * 4 + 0][hh] + red[nq2 * 4 + 1][hh]
                         + red[nq2 * 4 + 2][hh] + red[nq2 * 4 + 3][hh];
    }
}

// ---------------------------------------------------------------------------
// Head kernel v2: 256 CTAs x 8 nodes, warp-per-node. Double-buffered weights
// (float2-packed (h, h+32), k-major stride-33), prefetch-overlap staging.
// Inter-layer sync is __syncwarp only; __syncthreads only guards weight bufs.
// ---------------------------------------------------------------------------
__global__ void __launch_bounds__(256) k_head(const float* __restrict__ x,
                                              const float* __restrict__ We2n,
                                              const float* __restrict__ be2n,
                                              const float* __restrict__ Wn2n,
                                              const float* __restrict__ bn2n,
                                              const float* __restrict__ Wo1,
                                              const float* __restrict__ bo1,
                                              const float* __restrict__ Wo2,
                                              const float* __restrict__ bo2,
                                              float* __restrict__ out) {
    __shared__ float2 wA[66 * 33];   // layer1 weights, then reused for Wo1
    __shared__ float2 wB[64 * 33];   // layer2 weights
    __shared__ float sio[8][64];
    __shared__ float sb[3][64];
    __shared__ float swo2[128];
    __shared__ float sb2o[2];
    __shared__ float sxn[8][2];

    int t = threadIdx.x;
    int w = t >> 5;
    int lane = t & 31;
    int nbase = blockIdx.x * 8;

    // ---- stage layer-1 weights + node state + constants ----
    for (int idx = t; idx < 2048; idx += 256) {
        int k = idx & 63, h = idx >> 6;
        wA[k * 33 + h] = make_float2(We2n[h * 64 + k], We2n[(h + 32) * 64 + k]);
    }
    {
        int idx = t;
        sio[idx >> 6][idx & 63] = g_s[(nbase + (idx >> 6)) * 64 + (idx & 63)];
        idx = t + 256;
        sio[idx >> 6][idx & 63] = g_s[(nbase + (idx >> 6)) * 64 + (idx & 63)];
    }
    if (t < 64) { sb[0][t] = be2n[t]; sb[1][t] = bn2n[t]; sb[2][t] = bo1[t]; }
    if (t < 128) swo2[t] = Wo2[t];
    if (t < 2) sb2o[t] = bo2[t];
    if (t < 16) sxn[t >> 1][t & 1] = x[(nbase + (t >> 1)) * 2 + (t & 1)];
    __syncthreads();

    // ---- prefetch layer-2 weights into regs; compute L1; STS; barrier ----
    float2 pf[8];
    #pragma unroll
    for (int c = 0; c < 8; ++c) {
        int idx = t + c * 256;
        int k = idx & 63, h = idx >> 6;
        pf[c] = make_float2(Wn2n[h * 64 + k], Wn2n[(h + 32) * 64 + k]);
    }
    float a0 = sb[0][lane], a1 = sb[0][32 + lane];
    #pragma unroll 16
    for (int k = 0; k < 64; ++k) {
        float2 wv = wA[k * 33 + lane];
        float xv = sio[w][k];
        a0 = fmaf(wv.x, xv, a0);
        a1 = fmaf(wv.y, xv, a1);
    }
    a0 = fmaxf(a0, 0.f); a1 = fmaxf(a1, 0.f);
    __syncwarp();
    sio[w][lane] = a0; sio[w][32 + lane] = a1;
    #pragma unroll
    for (int c = 0; c < 8; ++c) {
        int idx = t + c * 256;
        int k = idx & 63, h = idx >> 6;
        wB[k * 33 + h] = pf[c];
    }
    __syncthreads();   // wB ready; all warps done reading wA

    // ---- prefetch Wo1 into regs; compute L2; STS Wo1 -> wA; barrier ----
    float2 pfo[9];
    #pragma unroll
    for (int c = 0; c < 9; ++c) {
        int idx = t + c * 256;
        if (idx < 2112) {
            int cc = idx / 32, h = idx & 31;   // cc = 0..65
            pfo[c] = make_float2(Wo1[h * 66 + cc], Wo1[(h + 32) * 66 + cc]);
        }
    }
    a0 = sb[1][lane]; a1 = sb[1][32 + lane];
    #pragma unroll 16
    for (int k = 0; k < 64; ++k) {
        float2 wv = wB[k * 33 + lane];
        float xv = sio[w][k];
        a0 = fmaf(wv.x, xv, a0);
        a1 = fmaf(wv.y, xv, a1);
    }
    a0 = fmaxf(a0, 0.f); a1 = fmaxf(a1, 0.f);
    __syncwarp();
    sio[w][lane] = a0; sio[w][32 + lane] = a1;
    #pragma unroll
    for (int c = 0; c < 9; ++c) {
        int idx = t + c * 256;
        if (idx < 2112) {
            int cc = idx / 32, h = idx & 31;
            wA[cc * 33 + h] = pfo[c];
        }
    }
    __syncthreads();   // Wo1 in wA; all warps done reading wB

    // ---- L3: vec = cat(x, h2) ----
    a0 = sb[2][lane]; a1 = sb[2][32 + lane];
    {
        float x0 = sxn[w][0], x1 = sxn[w][1];
        float2 wv0 = wA[0 * 33 + lane];
        float2 wv1 = wA[1 * 33 + lane];
        a0 = fmaf(wv0.x, x0, fmaf(wv1.x, x1, a0));
        a1 = fmaf(wv0.y, x0, fmaf(wv1.y, x1, a1));
    }
    #pragma unroll 16
    for (int k = 0; k < 64; ++k) {
        float2 wv = wA[(k + 2) * 33 + lane];
        float xv = sio[w][k];
        a0 = fmaf(wv.x, xv, a0);
        a1 = fmaf(wv.y, xv, a1);
    }
    a0 = fmaxf(a0, 0.f); a1 = fmaxf(a1, 0.f);   // h3 in regs

    // ---- output: per-warp dual dot + shfl reduce ----
    #pragma unroll
    for (int o = 0; o < 2; ++o) {
        float p = swo2[o * 64 + lane] * a0 + swo2[o * 64 + 32 + lane] * a1;
        p += __shfl_down_sync(0xFFFFFFFFu, p, 16);
        p += __shfl_down_sync(0xFFFFFFFFu, p, 8);
        p += __shfl_down_sync(0xFFFFFFFFu, p, 4);
        p += __shfl_down_sync(0xFFFFFFFFu, p, 2);
        p += __shfl_down_sync(0xFFFFFFFFu, p, 1);
        if (lane == 0) out[(nbase + w) * 2 + o] = sb2o[o] + p;
    }
}

// ---------------------------------------------------------------------------
extern "C" void kernel_launch(void* const* d_in, const int* in_sizes, int n_in,
                              void* d_out, int out_size) {
    const float* input = (const float*)d_in[0];
    const float* adj   = (const float*)d_in[1];
    const float* W_n2e = (const float*)d_in[2];
    const float* b_n2e = (const float*)d_in[3];
    const float* W_e2e = (const float*)d_in[4];
    const float* b_e2e = (const float*)d_in[5];
    const float* W_e2n = (const float*)d_in[6];
    const float* b_e2n = (const float*)d_in[7];
    const float* W_n2n = (const float*)d_in[8];
    const float* b_n2n = (const float*)d_in[9];
    const float* W_o1  = (const float*)d_in[10];
    const float* b_o1  = (const float*)d_in[11];
    const float* W_o2  = (const float*)d_in[12];
    const float* b_o2  = (const float*)d_in[13];
    float* out = (float*)d_out;

    k_edge_mma<<<NB * NN, 256>>>(input, adj, W_n2e, b_n2e, W_e2e, b_e2e);
    k_head<<<NB * NN / 8, 256>>>(input, W_e2n, b_e2n, W_n2n, b_n2n,
                                 W_o1, b_o1, W_o2, b_o2, out);
}